// round 4
// baseline (speedup 1.0000x reference)
#include <cuda_runtime.h>
#include <math_constants.h>

// Quanvolutional layer, analytically collapsed (Heisenberg picture):
// with z_q = cos(w_q) * cos(pi * x_q):
//   <Z0> = z1*...*z8,  <Z1> = z0*z1,  <Z2> = z0*z1*z2,  <Z3> = z0*z1*z2*z3
// summed over 3 channels. Output = raw reshape [94,94,4] -> out[(i*94+j)*4+f].
//
// R3: warp-shuffle dedup. Each lane loads ONE column of the 3x3 window
// (9 LDG, coalesced) and computes cos(pi*x) once per element (9 MUFU);
// neighbor columns arrive via __shfl_down. 32 lanes -> 30 output columns.
// Cuts LDG 27->9 and MUFU 36->18 per thread vs R2.

#define KH 96
#define HOUT 94

__global__ __launch_bounds__(128)
void quanv_kernel(const float* __restrict__ x,
                  const float* __restrict__ w,
                  float* __restrict__ out) {
    const int warp = threadIdx.x >> 5;
    const int lane = threadIdx.x & 31;
    const int task = blockIdx.x * 4 + warp;       // 0..375
    if (task >= HOUT * 4) return;                 // whole-warp uniform exit
    const int i = task >> 2;                      // output row 0..93
    const int g = task & 3;                       // column group
    const int j = g * 30 + lane;                  // this lane's load column

    // 9 weight cosines (broadcast loads)
    float cw[9];
#pragma unroll
    for (int q = 0; q < 9; q++) cw[q] = __cosf(__ldg(w + q));

    // Each lane: one column, 3 rows, 3 channels. Clamp OOB columns (their
    // results only feed guarded-out outputs).
    const int jc = (j < KH) ? j : (KH - 1);
    float y[3][3];
#pragma unroll
    for (int c = 0; c < 3; c++) {
        const float* xc = x + c * KH * KH + i * KH + jc;
#pragma unroll
        for (int r = 0; r < 3; r++)
            y[c][r] = __cosf(CUDART_PI_F * __ldg(xc + r * KH));
    }

    float ev0 = 0.f, ev1 = 0.f, ev2 = 0.f, ev3 = 0.f;

#pragma unroll
    for (int c = 0; c < 3; c++) {
        float z[9];
#pragma unroll
        for (int r = 0; r < 3; r++) {
            float y0 = y[c][r];
            float y1 = __shfl_down_sync(0xFFFFFFFFu, y0, 1);
            float y2 = __shfl_down_sync(0xFFFFFFFFu, y0, 2);
            z[r * 3 + 0] = cw[r * 3 + 0] * y0;
            z[r * 3 + 1] = cw[r * 3 + 1] * y1;
            z[r * 3 + 2] = cw[r * 3 + 2] * y2;
        }
        float p01   = z[0] * z[1];
        float p012  = p01 * z[2];
        float p0123 = p012 * z[3];
        ev1 += p01;
        ev2 += p012;
        ev3 += p0123;
        float a = z[1] * z[2];
        float b = z[3] * z[4];
        float d = z[5] * z[6];
        float e = z[7] * z[8];
        ev0 += (a * b) * (d * e);
    }

    if (lane < 30 && j < HOUT)
        reinterpret_cast<float4*>(out)[i * HOUT + j] =
            make_float4(ev0, ev1, ev2, ev3);
}

extern "C" void kernel_launch(void* const* d_in, const int* in_sizes, int n_in,
                              void* d_out, int out_size) {
    const float* x = (const float*)d_in[0];   // [1,3,96,96]
    const float* w = (const float*)d_in[1];   // [1,9]
    float* out = (float*)d_out;               // [1,4,94,94]

    // 94 rows x 4 column-groups = 376 warp-tasks, 4 warps/block -> 94 blocks
    quanv_kernel<<<94, 128>>>(x, w, out);
}

// round 5
// speedup vs baseline: 1.3354x; 1.3354x over previous
#include <cuda_runtime.h>
#include <math_constants.h>

// Quanvolutional layer, analytically collapsed (Heisenberg picture):
// with z_q = cos(w_q) * cos(pi * x_q):
//   <Z0> = z1*...*z8,  <Z1> = z0*z1,  <Z2> = z0*z1*z2,  <Z3> = z0*z1*z2*z3
// summed over 3 channels. Output = raw reshape [94,94,4] -> out[(i*94+j)*4+f].
//
// R4: weight factorization. The cw products separate from the channel sum:
//   ev_f = W_f * sum_c P_f(y_c),  W0=cw1..cw8, W1=cw0*cw1, W2=W1*cw2, W3=W2*cw3
// so the inner loop touches only raw cos(pi*x) products (27 cw-muls -> 4).
// Warp-shuffle column dedup as in R3: 9 LDG + 9 MUFU per thread.

#define KH 96
#define HOUT 94

__global__ __launch_bounds__(128)
void quanv_kernel(const float* __restrict__ x,
                  const float* __restrict__ w,
                  float* __restrict__ out) {
    const int warp = threadIdx.x >> 5;
    const int lane = threadIdx.x & 31;
    const int task = blockIdx.x * 4 + warp;       // 0..375, exact
    const int i = task >> 2;                      // output row 0..93
    const int g = task & 3;                       // column group
    const int j = g * 30 + lane;                  // this lane's load column
    const int jc = (j < KH) ? j : (KH - 1);       // clamp OOB lanes 30/31 @ g=3

    // Weight constants: only 4 products of the 9 cw are ever needed.
    float cw[9];
#pragma unroll
    for (int q = 0; q < 9; q++) cw[q] = __cosf(__ldg(w + q));
    float W1 = cw[0] * cw[1];
    float W2 = W1 * cw[2];
    float W3 = W2 * cw[3];
    float W0 = (cw[1] * cw[2]) * (cw[3] * cw[4]) *
               (cw[5] * cw[6]) * (cw[7] * cw[8]);

    // One column per lane: 3 rows x 3 channels, cos(pi*x) once per element.
    float y[3][3];
#pragma unroll
    for (int c = 0; c < 3; c++) {
        const float* xc = x + c * KH * KH + i * KH + jc;
#pragma unroll
        for (int r = 0; r < 3; r++)
            y[c][r] = __cosf(CUDART_PI_F * __ldg(xc + r * KH));
    }

    float S0 = 0.f, S1 = 0.f, S2 = 0.f, S3 = 0.f;

#pragma unroll
    for (int c = 0; c < 3; c++) {
        // Rows of the 3x3 window; columns j, j+1, j+2 via shuffle.
        float a0 = y[c][0];
        float a1 = __shfl_down_sync(0xFFFFFFFFu, a0, 1);
        float a2 = __shfl_down_sync(0xFFFFFFFFu, a0, 2);
        float b0 = y[c][1];
        float b1 = __shfl_down_sync(0xFFFFFFFFu, b0, 1);
        float b2 = __shfl_down_sync(0xFFFFFFFFu, b0, 2);
        float c0 = y[c][2];
        float c1 = __shfl_down_sync(0xFFFFFFFFu, c0, 1);
        float c2 = __shfl_down_sync(0xFFFFFFFFu, c0, 2);

        float t01   = a0 * a1;            // q0*q1
        float t012  = t01 * a2;           // q0*q1*q2
        float t0123 = t012 * b0;          // q0..q3
        S1 += t01;
        S2 += t012;
        S3 += t0123;
        // q1*q2*...*q8
        S0 += ((a1 * a2) * (b0 * b1)) * ((b2 * c0) * (c1 * c2));
    }

    if (lane < 30 && j < HOUT)
        reinterpret_cast<float4*>(out)[i * HOUT + j] =
            make_float4(W0 * S0, W1 * S1, W2 * S2, W3 * S3);
}

extern "C" void kernel_launch(void* const* d_in, const int* in_sizes, int n_in,
                              void* d_out, int out_size) {
    const float* x = (const float*)d_in[0];   // [1,3,96,96]
    const float* w = (const float*)d_in[1];   // [1,9]
    float* out = (float*)d_out;               // [1,4,94,94]

    // 94 rows x 4 column-groups = 376 warp-tasks, 4 warps/block -> 94 blocks
    quanv_kernel<<<94, 128>>>(x, w, out);
}